// round 17
// baseline (speedup 1.0000x reference)
#include <cuda_runtime.h>

// Problem constants: N=1024 agents, H=64 hidden.
#define Nn 1024
#define Hh 64
#define EE (Nn * (Nn - 1))   // 1047552 edges

// Factored first layer + relu-elimination scalars:
//   gA[i][k] = b1[k] + sum_c emb[i][c] * W1[c][k]
//   gB[j][k] =         sum_c emb[j][c] * W1[64+c][k]
//   gGamma[i] = b2 + 0.5 * <W2, gA[i]>,   gDelta[j] = 0.5 * <W2, gB[j]>
__device__ float gA[Nn * Hh];
__device__ float gB[Nn * Hh];
__device__ float gGamma[Nn];
__device__ float gDelta[Nn];

// ---------------------------------------------------------------------------
// Kernel A (stream 1, concurrent with prep): the two edge_index planes.
//   e = i*1023 + (j - (j>i));  inverse: i = e/1023, r = e%1023, j = r + (r>=i)
// 256 CTAs x 256 threads, 4 float4-quads per thread, coalesced stores.
// No dependency on anything computed — pure fork branch.
// ---------------------------------------------------------------------------
__global__ void __launch_bounds__(256) idx_kernel(float* __restrict__ out) {
    const unsigned tid = blockIdx.x * 256 + threadIdx.x;   // 65536 threads
    const unsigned nquads = EE / 4;                        // 261888
#pragma unroll 4
    for (unsigned q = tid; q < nquads; q += 65536) {
        const unsigned e0 = q * 4;
        float4 vi, vj;
        float* pi = &vi.x;
        float* pj = &vj.x;
#pragma unroll
        for (int u = 0; u < 4; u++) {
            const unsigned e = e0 + u;
            const unsigned i = e / 1023u;
            const unsigned r = e - i * 1023u;
            const unsigned j = r + (r >= i ? 1u : 0u);
            pi[u] = (float)i;
            pj[u] = (float)j;
        }
        *reinterpret_cast<float4*>(out + e0) = vi;
        *reinterpret_cast<float4*>(out + EE + e0) = vj;
    }
}

// ---------------------------------------------------------------------------
// Kernel B (stream 0): HALF-STAGED prep (round 16). 256 CTAs x 256 threads,
// CTA parity picks a 16 KB W1 half; warp = one row; lane owns 2 output cols.
// gamma/delta via in-warp dot + butterfly reduce.
// ---------------------------------------------------------------------------
__global__ void __launch_bounds__(256) prep_kernel(const float* __restrict__ emb,
                                                   const float* __restrict__ W1,
                                                   const float* __restrict__ b1,
                                                   const float* __restrict__ W2,
                                                   const float* __restrict__ b2ptr) {
    __shared__ float sW1h[64 * 64];   // 16 KB: one half of W1

    const int t = threadIdx.x;
    const int c = blockIdx.x;
    const int half = c & 1;
    const float* w1h = W1 + half * Hh * Hh;

#pragma unroll
    for (int q = t; q < 1024; q += 256)
        reinterpret_cast<float4*>(sW1h)[q] = reinterpret_cast<const float4*>(w1h)[q];
    __syncthreads();

    const int wid = t >> 5;
    const int lane = t & 31;
    const int row = (c >> 1) * 8 + wid;
    const int k = 2 * lane;

    float acc0 = 0.f, acc1 = 0.f;
    const float* embRow = emb + row * Hh;
#pragma unroll
    for (int cc = 0; cc < Hh; cc += 4) {
        const float4 e4 = *reinterpret_cast<const float4*>(embRow + cc);  // broadcast
        const float2 w0 = *reinterpret_cast<const float2*>(&sW1h[(cc + 0) * Hh + k]);
        const float2 w1v = *reinterpret_cast<const float2*>(&sW1h[(cc + 1) * Hh + k]);
        const float2 w2v = *reinterpret_cast<const float2*>(&sW1h[(cc + 2) * Hh + k]);
        const float2 w3v = *reinterpret_cast<const float2*>(&sW1h[(cc + 3) * Hh + k]);
        acc0 = fmaf(e4.x, w0.x, acc0); acc1 = fmaf(e4.x, w0.y, acc1);
        acc0 = fmaf(e4.y, w1v.x, acc0); acc1 = fmaf(e4.y, w1v.y, acc1);
        acc0 = fmaf(e4.z, w2v.x, acc0); acc1 = fmaf(e4.z, w2v.y, acc1);
        acc0 = fmaf(e4.w, w3v.x, acc0); acc1 = fmaf(e4.w, w3v.y, acc1);
    }

    float2 o;
    if (half == 0) {
        const float2 bb = *reinterpret_cast<const float2*>(b1 + k);
        o.x = acc0 + bb.x; o.y = acc1 + bb.y;
        *reinterpret_cast<float2*>(&gA[row * Hh + k]) = o;
    } else {
        o.x = acc0; o.y = acc1;
        *reinterpret_cast<float2*>(&gB[row * Hh + k]) = o;
    }

    const float2 wv = *reinterpret_cast<const float2*>(W2 + k);
    float part = o.x * wv.x + o.y * wv.y;
#pragma unroll
    for (int off = 16; off > 0; off >>= 1)
        part += __shfl_xor_sync(0xffffffffu, part, off);
    if (lane == 0) {
        if (half == 0) gGamma[row] = b2ptr[0] + 0.5f * part;
        else           gDelta[row] = 0.5f * part;
    }
}

// ---------------------------------------------------------------------------
// Kernel C: per-pair MLP (round-14 core, WEIGHTS-ONLY epilogue):
//   x(i,j) = gGamma[i] + gDelta[j] + sum_k (W2[k]/2) * |A_ik + B_jk|
// Grid 32x32 = 1024 CTAs, 64 threads, 4x4 micro-tile (16 pairs/thread).
// Bank analysis (TPAD=76, quad = 12*row mod 32): rows r+8u walk 8 distinct
// quads; A rows broadcast per 8-lane phase -> all LDS.128 conflict-free.
// Epilogue: 16 STG.32 (weight plane only; index planes done by idx_kernel).
// ---------------------------------------------------------------------------
#define TSI 32
#define TSJ 32
#define TPAD 76

__global__ void __launch_bounds__(64, 11) pair_kernel(const float* __restrict__ W2,
                                                      float* __restrict__ out) {
    __shared__ float sA[TSI * TPAD];
    __shared__ float sB[TSJ * TPAD];
    __shared__ float sW2[64];    // pre-scaled by 0.5
    __shared__ float sGam[TSI];
    __shared__ float sDel[TSJ];

    const int t = threadIdx.x;
    const int tx = t & 7;
    const int ty = t >> 3;
    const int i0 = blockIdx.y * TSI;
    const int j0 = blockIdx.x * TSJ;

#pragma unroll
    for (int q = t; q < 1024; q += 64) {
        if (q < 512) {
            const int r = q >> 4, c4 = (q & 15) * 4;
            *reinterpret_cast<float4*>(&sA[r * TPAD + c4]) =
                *reinterpret_cast<const float4*>(&gA[(i0 + r) * Hh + c4]);
        } else {
            const int q2 = q - 512;
            const int r = q2 >> 4, c4 = (q2 & 15) * 4;
            *reinterpret_cast<float4*>(&sB[r * TPAD + c4]) =
                *reinterpret_cast<const float4*>(&gB[(j0 + r) * Hh + c4]);
        }
    }
    sW2[t] = 0.5f * W2[t];
    if (t < 32) sGam[t] = gGamma[i0 + t];
    else        sDel[t - 32] = gDelta[j0 + (t - 32)];
    __syncthreads();

    float acc[4][4] = {};

    const float* aBase = &sA[ty * TPAD];
    const float* bBase = &sB[tx * TPAD];

#pragma unroll
    for (int k = 0; k < Hh; k += 4) {
        const float4 wq = *reinterpret_cast<const float4*>(&sW2[k]);
        float4 av[4], bv[4];
#pragma unroll
        for (int u = 0; u < 4; u++)
            av[u] = *reinterpret_cast<const float4*>(aBase + (8 * u) * TPAD + k);
#pragma unroll
        for (int u = 0; u < 4; u++)
            bv[u] = *reinterpret_cast<const float4*>(bBase + (8 * u) * TPAD + k);

#pragma unroll
        for (int ii = 0; ii < 4; ii++) {
#pragma unroll
            for (int jj = 0; jj < 4; jj++) {
                float a = acc[ii][jj];
                a = fmaf(fabsf(av[ii].x + bv[jj].x), wq.x, a);
                a = fmaf(fabsf(av[ii].y + bv[jj].y), wq.y, a);
                a = fmaf(fabsf(av[ii].z + bv[jj].z), wq.z, a);
                a = fmaf(fabsf(av[ii].w + bv[jj].w), wq.w, a);
                acc[ii][jj] = a;
            }
        }
    }

#pragma unroll
    for (int ii = 0; ii < 4; ii++) {
        const int i = i0 + ty + 8 * ii;
        const float gi = sGam[ty + 8 * ii];
#pragma unroll
        for (int jj = 0; jj < 4; jj++) {
            const int j = j0 + tx + 8 * jj;
            if (j == i) continue;
            const int e = i * (Nn - 1) + j - (j > i ? 1 : 0);
            const float x = acc[ii][jj] + gi + sDel[tx + 8 * jj];
            const float ex = __expf(-x);
            out[2 * EE + e] = __fdividef(1.0f, 1.0f + ex);
        }
    }
}

// ---------------------------------------------------------------------------
// Launch with a capture-legal fork/join:
//   stream 0: prep ──────────────┐
//   stream 1: idx  (concurrent) ─┴→ join → pair
// Streams/events are created fresh per call (host objects, not device
// memory; kernel_launch is invoked only a handful of times, never on graph
// replays). They are deliberately not destroyed within the call — the
// capture the harness owns is still active when we return.
// ---------------------------------------------------------------------------
extern "C" void kernel_launch(void* const* d_in, const int* in_sizes, int n_in,
                              void* d_out, int out_size) {
    const float* emb = (const float*)d_in[0];  // [1024, 64]
    const float* W1  = (const float*)d_in[1];  // [128, 64]
    const float* b1  = (const float*)d_in[2];  // [64]
    const float* W2  = (const float*)d_in[3];  // [64, 1]
    const float* b2  = (const float*)d_in[4];  // [1]
    float* out = (float*)d_out;

    cudaStream_t s1;
    cudaEvent_t evFork, evJoin;
    cudaStreamCreateWithFlags(&s1, cudaStreamNonBlocking);
    cudaEventCreateWithFlags(&evFork, cudaEventDisableTiming);
    cudaEventCreateWithFlags(&evJoin, cudaEventDisableTiming);

    // Fork: bring s1 into the (possibly active) capture of the default stream.
    cudaEventRecord(evFork, 0);
    cudaStreamWaitEvent(s1, evFork, 0);

    prep_kernel<<<256, 256, 0, 0>>>(emb, W1, b1, W2, b2);   // stream 0
    idx_kernel<<<256, 256, 0, s1>>>(out);                   // stream 1 (parallel)

    // Join: pair depends on both branches.
    cudaEventRecord(evJoin, s1);
    cudaStreamWaitEvent(0, evJoin, 0);

    pair_kernel<<<dim3(32, 32), 64, 0, 0>>>(W2, out);
}